// round 16
// baseline (speedup 1.0000x reference)
#include <cuda_runtime.h>
#include <cuda_bf16.h>
#include <math.h>
#include <cstdint>

// ---- problem dims ----
#define BB   4
#define LL   24
#define NNP  512
#define DIMC 1024
#define JJ   24
#define MMS  64
#define FDC  128
#define OUTC 72
#define NT   (LL*NNP)
#define TOK  (BB*NT)

#define SEG_OFF  (BB*OUTC)
#define SEG_SIZE (BB*LL*JJ*NNP)
#define LOSS_OFF (SEG_OFF + SEG_SIZE)

#define TBB 128
#define NBLK_B (BB*(NT/TBB))           // 384

// ---- device scratch ----
__device__ __nv_bfloat16 g_mem_hi[FDC*JJ*MMS];    // [d][slot]
__device__ __nv_bfloat16 g_mem_lo[FDC*JJ*MMS];
__device__ __nv_bfloat16 g_w_hi[16*160*64];       // [ktile64][row][k-in-tile]
__device__ __nv_bfloat16 g_w_lo[16*160*64];
__device__ float    g_lossPartial[NBLK_B];
__device__ unsigned g_skl[BB*FDC];

__device__ __forceinline__ unsigned encf(float f) {
    unsigned u = __float_as_uint(f);
    return (u & 0x80000000u) ? ~u : (u | 0x80000000u);
}
__device__ __forceinline__ float decf(unsigned u) {
    return (u & 0x80000000u) ? __uint_as_float(u & 0x7FFFFFFFu)
                             : __uint_as_float(~u);
}

__device__ __forceinline__ uint32_t smem_u32(const void* p) {
    uint32_t a;
    asm("{ .reg .u64 t; cvta.to.shared.u64 t, %1; cvt.u32.u64 %0, t; }" : "=r"(a) : "l"(p));
    return a;
}

// ---- mma (non-volatile: deps carried by "+f" accumulator constraints) ----
__device__ __forceinline__ void mma16816(float* d, const uint32_t* a,
                                         uint32_t b0, uint32_t b1) {
    asm("mma.sync.aligned.m16n8k16.row.col.f32.bf16.bf16.f32 "
        "{%0,%1,%2,%3}, {%4,%5,%6,%7}, {%8,%9}, {%0,%1,%2,%3};"
        : "+f"(d[0]), "+f"(d[1]), "+f"(d[2]), "+f"(d[3])
        : "r"(a[0]), "r"(a[1]), "r"(a[2]), "r"(a[3]), "r"(b0), "r"(b1));
}
#define LDSM_X4(r, a) asm volatile("ldmatrix.sync.aligned.m8n8.x4.shared.b16 {%0,%1,%2,%3}, [%4];" \
    : "=r"((r)[0]),"=r"((r)[1]),"=r"((r)[2]),"=r"((r)[3]) : "r"(a))
#define LDSM_X4T(r, a) asm volatile("ldmatrix.sync.aligned.m8n8.x4.trans.shared.b16 {%0,%1,%2,%3}, [%4];" \
    : "=r"((r)[0]),"=r"((r)[1]),"=r"((r)[2]),"=r"((r)[3]) : "r"(a))
#define CP_ASYNC16(dst, src) asm volatile("cp.async.cg.shared.global [%0], [%1], 16;" :: "r"(dst), "l"(src))
#define CP_COMMIT() asm volatile("cp.async.commit_group;" ::: "memory")
#define CP_WAIT0() asm volatile("cp.async.wait_group 0;" ::: "memory")
#define CP_WAIT1() asm volatile("cp.async.wait_group 1;" ::: "memory")

__device__ __forceinline__ uint32_t pack2(__nv_bfloat16 x, __nv_bfloat16 y) {
    __nv_bfloat162 v; v.x = x; v.y = y;
    return *(uint32_t*)&v;
}
__device__ __forceinline__ void hilo(float v, __nv_bfloat16& h, __nv_bfloat16& l) {
    h = __float2bfloat16(v);
    l = __float2bfloat16(v - __bfloat162float(h));
}

// fused prep: mem -> bf16 hi/lo, W (seg_w|pc_w) -> bf16 hi/lo ktile64-major, g_skl init
__global__ void kPrep(const float* __restrict__ memw,
                      const float* __restrict__ seg_w, const float* __restrict__ pc_w) {
    int i = blockIdx.x*blockDim.x + threadIdx.x;
    if (i < BB*FDC) g_skl[i] = 0u;
    if (i < 16*160*64) {
        const int kk = i & 63, row = (i >> 6) % 160, kt = i / (160*64);
        float v = 0.f;
        if (row < JJ)            v = seg_w[row*DIMC + kt*64 + kk];
        else if (row < JJ + FDC) v = pc_w[(row - JJ)*DIMC + kt*64 + kk];
        __nv_bfloat16 h, l; hilo(v, h, l);
        g_w_hi[i] = h;  g_w_lo[i] = l;
    }
    if (i < FDC*JJ*MMS) {
        float v = memw[i];
        __nv_bfloat16 h, l; hilo(v, h, l);
        g_mem_hi[i] = h;  g_mem_lo[i] = l;
    }
}

// ---- fused kernel smem layout ----
// phase A (proj): 2 buffers of 82944 -> [0, 165888)
#define KA_AH 0
#define KA_AL 18432
#define KA_WH 36864
#define KA_WL 59904
#define KA_BUF 82944
// phase B: A1 tiles overlay kA buf0; 4 mem buffers (2 pairs)
#define OFF_A1H  0          // 128 x 136 bf16 = 34816
#define OFF_A1L  34816
#define OFF_B2H0 69632      // 4 bufs x 18432 -> 143360
#define OFF_B2L0 143360     // 4 bufs x 18432 -> 217088
#define OFF_SEG  217088     // 128*25 floats = 12800
#define OFF_PSUM 229888
#define OFF_DMAX 230400
#define OFF_WSUM 230912
#define SMEM_AB  230976

__global__ __launch_bounds__(512, 1) void kAB(const float* __restrict__ feat,
        const float* __restrict__ seg_b, const float* __restrict__ pc_b,
        float* __restrict__ out)
{
    extern __shared__ char sm[];
    const uint32_t smb = smem_u32(sm);
    const int tid  = threadIdx.x;
    const int lane = tid & 31;
    const int wid  = tid >> 5;
    const int t0   = blockIdx.x * 128;
    const int b    = blockIdx.x / (NT/TBB);
    const int n0   = (blockIdx.x % (NT/TBB)) * TBB;

    __nv_bfloat16* A1H = (__nv_bfloat16*)(sm + OFF_A1H);
    __nv_bfloat16* A1L = (__nv_bfloat16*)(sm + OFF_A1L);
    float*    segS  = (float*)(sm + OFF_SEG);
    float*    psumP = (float*)(sm + OFF_PSUM);
    unsigned* dmax  = (unsigned*)(sm + OFF_DMAX);
    float*    wsum  = (float*)(sm + OFF_WSUM);

    auto prefetch = [&](int chn, int bufn) {
        const int k0 = chn*MMS;
        const uint32_t dH = smb + OFF_B2H0 + bufn*18432;
        const uint32_t dL = smb + OFF_B2L0 + bufn*18432;
#pragma unroll
        for (int it = 0; it < 2; it++) {
            const int p = tid + it*512, d = p >> 3, j = p & 7;
            CP_ASYNC16(dH + d*144 + j*16, (const char*)g_mem_hi + ((size_t)d*(JJ*MMS) + k0)*2 + j*16);
            CP_ASYNC16(dL + d*144 + j*16, (const char*)g_mem_lo + ((size_t)d*(JJ*MMS) + k0)*2 + j*16);
        }
    };

    // ================= phase A: seg+pc projection =================
    {
        const int wm   = wid >> 1, wn = wid & 1;
        const int row0 = wm*16, col0 = wn*80;

        const uint32_t offA_lm = (uint32_t)(((lane & 7) + ((lane >> 3) & 1)*8)*144 + (lane >> 4)*16);
        const uint32_t offB_lm = (uint32_t)(((lane & 7) + ((lane >> 4) & 1)*8)*144 + ((lane >> 3) & 1)*16);

        float acc[10][4];
#pragma unroll
        for (int nt = 0; nt < 10; nt++)
#pragma unroll
            for (int r = 0; r < 4; r++) acc[nt][r] = 0.f;

        float4 fA[4];

        auto ldg_tile = [&](int k0) {
#pragma unroll
            for (int it = 0; it < 4; it++) {
                const int p = tid + it*512, r = p >> 4, c4 = (p & 15)*4;
                fA[it] = *(const float4*)&feat[(size_t)(t0 + r)*DIMC + k0 + c4];
            }
        };
        auto sts_tile = [&](int buf) {
            const uint32_t aH = buf*KA_BUF + KA_AH, aL = buf*KA_BUF + KA_AL;
#pragma unroll
            for (int it = 0; it < 4; it++) {
                const int p = tid + it*512, r = p >> 4, c4 = (p & 15)*4;
                const float4 v = fA[it];
                __nv_bfloat16 h0,l0,h1,l1,h2,l2,h3,l3;
                hilo(v.x,h0,l0); hilo(v.y,h1,l1); hilo(v.z,h2,l2); hilo(v.w,h3,l3);
                *(uint2*)(sm + aH + r*144 + c4*2) = uint2{pack2(h0,h1), pack2(h2,h3)};
                *(uint2*)(sm + aL + r*144 + c4*2) = uint2{pack2(l0,l1), pack2(l2,l3)};
            }
        };
        auto cpW = [&](int kt, int buf) {
            const uint32_t wH = smb + buf*KA_BUF + KA_WH;
            const uint32_t wL = smb + buf*KA_BUF + KA_WL;
#pragma unroll
            for (int it2 = 0; it2 < 5; it2++) {
                const int q = tid + it2*512;
                const int qq = q - (q >= 1280 ? 1280 : 0);
                const int r = qq >> 3, j = qq & 7;
                const uint32_t dst = (q >= 1280 ? wL : wH) + r*144 + j*16;
                const char* src = (const char*)(q >= 1280 ? g_w_lo : g_w_hi)
                                + ((size_t)(kt*160 + r)*64 + j*8)*2;
                CP_ASYNC16(dst, src);
            }
        };

        cpW(0, 0); CP_COMMIT();
        ldg_tile(0);
        sts_tile(0);
        CP_WAIT0();
        __syncthreads();

        for (int it = 0; it < 16; it++) {
            const int buf = it & 1;
            if (it < 15) { ldg_tile((it + 1)*64); cpW(it + 1, buf ^ 1); CP_COMMIT(); }

            const uint32_t aH = smb + buf*KA_BUF + KA_AH, aL = smb + buf*KA_BUF + KA_AL;
            const uint32_t wH = smb + buf*KA_BUF + KA_WH, wL = smb + buf*KA_BUF + KA_WL;
#pragma unroll
            for (int ks = 0; ks < 4; ks++) {
                const uint32_t kkB = ks*32;
                uint32_t ah[4], al[4];
                LDSM_X4(ah, aH + offA_lm + row0*144 + kkB);
                LDSM_X4(al, aL + offA_lm + row0*144 + kkB);
#pragma unroll
                for (int ntp = 0; ntp < 5; ntp++) {
                    const uint32_t nOff = (col0 + ntp*16)*144;
                    uint32_t bh[4], bl[4];
                    LDSM_X4(bh, wH + offB_lm + nOff + kkB);
                    LDSM_X4(bl, wL + offB_lm + nOff + kkB);
                    mma16816(acc[2*ntp],   ah, bh[0], bh[1]);
                    mma16816(acc[2*ntp+1], ah, bh[2], bh[3]);
                    mma16816(acc[2*ntp],   ah, bl[0], bl[1]);
                    mma16816(acc[2*ntp+1], ah, bl[2], bl[3]);
                    mma16816(acc[2*ntp],   al, bh[0], bh[1]);
                    mma16816(acc[2*ntp+1], al, bh[2], bh[3]);
                }
            }
            if (it < 15) sts_tile(buf ^ 1);
            CP_WAIT0();
            __syncthreads();
        }

        // kA smem fully dead -> prefetch group0 (chunks 0,1); overlaps epilogue
        prefetch(0, 0); prefetch(1, 1); CP_COMMIT();
        if (tid < FDC) dmax[tid] = 0u;

        const int lq = lane >> 2, lr = lane & 3;
        // ---- pc epilogue: cols 24..151 -> A1 smem (hi/lo) ----
#pragma unroll
        for (int nt = 0; nt < 10; nt++) {
            const int c0 = col0 + nt*8 + lr*2;
            if (c0 < 24 || c0 >= 152) continue;
            const int d = c0 - 24;
#pragma unroll
            for (int half = 0; half < 2; half++) {
                const int row = row0 + lq + half*8;
                const float v0 = acc[nt][half*2 + 0] + pc_b[d];
                const float v1 = acc[nt][half*2 + 1] + pc_b[d + 1];
                __nv_bfloat16 h0,l0,h1,l1;
                hilo(v0,h0,l0); hilo(v1,h1,l1);
                *(__nv_bfloat162*)&A1H[row*136 + d] = __nv_bfloat162{h0,h1};
                *(__nv_bfloat162*)&A1L[row*136 + d] = __nv_bfloat162{l0,l1};
            }
        }
        // ---- seg epilogue: softmax -> out (global) + segS (smem) ----
        if (wn == 0) {
#pragma unroll
            for (int half = 0; half < 2; half++) {
                const int row = row0 + lq + half*8;
                float v[6];
#pragma unroll
                for (int nt = 0; nt < 3; nt++)
#pragma unroll
                    for (int q = 0; q < 2; q++)
                        v[nt*2 + q] = acc[nt][half*2 + q] + seg_b[nt*8 + lr*2 + q];
                float mx = v[0];
#pragma unroll
                for (int q = 1; q < 6; q++) mx = fmaxf(mx, v[q]);
                mx = fmaxf(mx, __shfl_xor_sync(0xffffffffu, mx, 1));
                mx = fmaxf(mx, __shfl_xor_sync(0xffffffffu, mx, 2));
                float s = 0.f;
#pragma unroll
                for (int q = 0; q < 6; q++) { v[q] = expf(v[q] - mx); s += v[q]; }
                s += __shfl_xor_sync(0xffffffffu, s, 1);
                s += __shfl_xor_sync(0xffffffffu, s, 2);
                const float inv = 1.f / s;
                const int t = t0 + row;
                const int bb = t / NT; const int rr = t % NT;
                const int l = rr / NNP; const int nn = rr % NNP;
                float* segout = out + SEG_OFF + ((size_t)(bb*LL + l)*JJ)*NNP + nn;
#pragma unroll
                for (int nt = 0; nt < 3; nt++)
#pragma unroll
                    for (int q = 0; q < 2; q++) {
                        const int j = nt*8 + lr*2 + q;
                        const float sv = v[nt*2 + q]*inv;
                        segout[(size_t)j*NNP] = sv;
                        segS[row*25 + j] = sv;
                    }
            }
        }
    }
    __syncthreads();   // A1 + segS visible to all

    // ================= phase B: forward_mem (group-of-2 chunks) =================
    {
        const int wm   = wid & 7;
        const int h    = wid >> 3;
        const int row0 = wm*16;
        const int g    = lane >> 2, t = lane & 3;

        const uint32_t offA1_lm = (uint32_t)((row0 + (lane & 7) + ((lane >> 3) & 1)*8)*272 + (lane >> 4)*16);
        const uint32_t offB1t4 = (uint32_t)(((lane & 7) + ((lane >> 3) & 1)*8)*144 + (lane >> 4)*16);
        const uint32_t offB2n4 = (uint32_t)((lane & 7)*144 + ((lane >> 3) & 1)*16 + (lane >> 4)*1152);

        float racc[16][4];
#pragma unroll
        for (int nt = 0; nt < 16; nt++)
#pragma unroll
            for (int r = 0; r < 4; r++) racc[nt][r] = 0.f;
        float psum0 = 0.f, psum1 = 0.f;
        const float invs = 0.088388347648318447f;

        for (int gr = 0; gr < JJ/2; ++gr) {
            CP_WAIT0();            // group gr resident
            __syncthreads();       // all warps done reading group gr-1's pair
            if (gr < JJ/2 - 1) {   // prefetch group gr+1 into the freed pair
                prefetch(2*gr + 2, (2*gr + 2) & 3);
                prefetch(2*gr + 3, (2*gr + 3) & 3);
                CP_COMMIT();
            }

#pragma unroll
            for (int sub = 0; sub < 2; sub++) {
                const int ch  = 2*gr + sub;
                const int buf = ch & 3;
                const uint32_t b2h = smb + OFF_B2H0 + buf*18432;
                const uint32_t b2l = smb + OFF_B2L0 + buf*18432;

                // ---- MMA1: logits[16 tok x 32 slots (this half)], K=128 ----
                float lacc[4][4];
#pragma unroll
                for (int nt = 0; nt < 4; nt++)
#pragma unroll
                    for (int r = 0; r < 4; r++) lacc[nt][r] = 0.f;
#pragma unroll
                for (int ks = 0; ks < 8; ks++) {
                    uint32_t ah[4], al[4];
                    LDSM_X4(ah, smb + OFF_A1H + offA1_lm + ks*32);
                    LDSM_X4(al, smb + OFF_A1L + offA1_lm + ks*32);
                    uint32_t bh0[4], bl0[4], bh1[4], bl1[4];
                    LDSM_X4T(bh0, b2h + offB1t4 + ks*2304 + (h*2 + 0)*32);
                    LDSM_X4T(bl0, b2l + offB1t4 + ks*2304 + (h*2 + 0)*32);
                    LDSM_X4T(bh1, b2h + offB1t4 + ks*2304 + (h*2 + 1)*32);
                    LDSM_X4T(bl1, b2l + offB1t4 + ks*2304 + (h*2 + 1)*32);
                    mma16816(lacc[0], ah, bh0[0], bh0[1]);
                    mma16816(lacc[1], ah, bh0[2], bh0[3]);
                    mma16816(lacc[2], ah, bh1[0], bh1[1]);
                    mma16816(lacc[3], ah, bh1[2], bh1[3]);
                    mma16816(lacc[0], ah, bl0[0], bl0[1]);
                    mma16816(lacc[1], ah, bl0[2], bl0[3]);
                    mma16816(lacc[2], ah, bl1[0], bl1[1]);
                    mma16816(lacc[3], ah, bl1[2], bl1[3]);
                    mma16816(lacc[0], al, bh0[0], bh0[1]);
                    mma16816(lacc[1], al, bh0[2], bh0[3]);
                    mma16816(lacc[2], al, bh1[0], bh1[1]);
                    mma16816(lacc[3], al, bh1[2], bh1[3]);
                }

                // ---- exp + pack attn A-fragments ----
                const float sv0 = segS[(row0 + g)*25 + ch] * invs;
                const float sv1 = segS[(row0 + g + 8)*25 + ch] * invs;
                uint32_t aHf[2][4], aLf[2][4];
#pragma unroll
                for (int nt = 0; nt < 4; nt++) {
                    const float p0 = __expf(lacc[nt][0]*sv0);
                    const float p1 = __expf(lacc[nt][1]*sv0);
                    const float p2 = __expf(lacc[nt][2]*sv1);
                    const float p3 = __expf(lacc[nt][3]*sv1);
                    psum0 += p0 + p1;  psum1 += p2 + p3;
                    __nv_bfloat16 h0,l0,h1,l1,h2,l2,h3,l3;
                    hilo(p0,h0,l0); hilo(p1,h1,l1); hilo(p2,h2,l2); hilo(p3,h3,l3);
                    const int ks2 = nt >> 1, hf = nt & 1;
                    aHf[ks2][hf*2 + 0] = pack2(h0, h1);
                    aHf[ks2][hf*2 + 1] = pack2(h2, h3);
                    aLf[ks2][hf*2 + 0] = pack2(l0, l1);
                    aLf[ks2][hf*2 + 1] = pack2(l2, l3);
                }

                // ---- MMA2: rec += attn @ mem, K = this half's 32 slots ----
#pragma unroll
                for (int ks2 = 0; ks2 < 2; ks2++) {
                    const uint32_t kbyte = h*64 + ks2*32;
#pragma unroll
                    for (int qp = 0; qp < 4; qp++) {
                        const int q0 = qp*2, q1 = qp*2 + 1;
                        uint32_t bh0[4], bl0[4], bh1[4], bl1[4];
                        LDSM_X4(bh0, b2h + offB2n4 + q0*2304 + kbyte);
                        LDSM_X4(bl0, b2l + offB2n4 + q0*2304 + kbyte);
                        LDSM_X4(bh1, b2h + offB2n4 + q1*2304 + kbyte);
                        LDSM_X4(bl1, b2l + offB2n4 + q1*2304 + kbyte);
                        mma16816(racc[2*q0],   aHf[ks2], bh0[0], bh0[1]);
                        mma16816(racc[2*q0+1], aHf[ks2], bh0[2], bh0[3]);
                        mma16816(racc[2*q1],   aHf[ks2], bh1[0], bh1[1]);
                        mma16816(racc[2*q1+1], aHf[ks2], bh1[2], bh1[3]);
                        mma16816(racc[2*q0],   aHf[ks2], bl0[0], bl0[1]);
                        mma16816(racc[2*q0+1], aHf[ks2], bl0[2], bl0[3]);
                        mma16816(racc[2*q1],   aHf[ks2], bl1[0], bl1[1]);
                        mma16816(racc[2*q1+1], aHf[ks2], bl1[2], bl1[3]);
                        mma16816(racc[2*q0],   aLf[ks2], bh0[0], bh0[1]);
                        mma16816(racc[2*q0+1], aLf[ks2], bh0[2], bh0[3]);
                        mma16816(racc[2*q1],   aLf[ks2], bh1[0], bh1[1]);
                        mma16816(racc[2*q1+1], aLf[ks2], bh1[2], bh1[3]);
                    }
                }
            }
        }

        psum0 += __shfl_xor_sync(0xffffffffu, psum0, 1);
        psum0 += __shfl_xor_sync(0xffffffffu, psum0, 2);
        psum1 += __shfl_xor_sync(0xffffffffu, psum1, 1);
        psum1 += __shfl_xor_sync(0xffffffffu, psum1, 2);

        __syncthreads();
        float* rs = (float*)(sm + OFF_B2H0);   // [128 tok][130] floats
        if (h == 1) {
            if (t == 0) { psumP[row0 + g] = psum0; psumP[row0 + g + 8] = psum1; }
#pragma unroll
            for (int nt = 0; nt < 16; nt++) {
                const int c = nt*8 + t*2;
                *(float2*)&rs[(row0 + g)*130 + c]     = float2{racc[nt][0], racc[nt][1]};
                *(float2*)&rs[(row0 + g + 8)*130 + c] = float2{racc[nt][2], racc[nt][3]};
            }
        }
        __syncthreads();

        if (h == 0) {
            const float inv0 = 1.f / (psum0 + psumP[row0 + g]);
            const float inv1 = 1.f / (psum1 + psumP[row0 + g + 8]);
            float lossloc = 0.f;
            const int r0g = row0 + g, r1g = row0 + g + 8;
#pragma unroll
            for (int nt = 0; nt < 16; nt++) {
                const int c = nt*8 + t*2;
                const float2 o0 = *(const float2*)&rs[r0g*130 + c];
                const float2 o1 = *(const float2*)&rs[r1g*130 + c];
                const float rec00 = (racc[nt][0] + o0.x)*inv0, rec01 = (racc[nt][1] + o0.y)*inv0;
                const float rec10 = (racc[nt][2] + o1.x)*inv1, rec11 = (racc[nt][3] + o1.y)*inv1;
                const __nv_bfloat162 ph0 = *(const __nv_bfloat162*)&A1H[r0g*136 + c];
                const __nv_bfloat162 pl0 = *(const __nv_bfloat162*)&A1L[r0g*136 + c];
                const __nv_bfloat162 ph1 = *(const __nv_bfloat162*)&A1H[r1g*136 + c];
                const __nv_bfloat162 pl1 = *(const __nv_bfloat162*)&A1L[r1g*136 + c];
                const float d0 = rec00 - (__bfloat162float(ph0.x) + __bfloat162float(pl0.x));
                const float d1 = rec01 - (__bfloat162float(ph0.y) + __bfloat162float(pl0.y));
                const float d2 = rec10 - (__bfloat162float(ph1.x) + __bfloat162float(pl1.x));
                const float d3 = rec11 - (__bfloat162float(ph1.y) + __bfloat162float(pl1.y));
                lossloc += d0*d0 + d1*d1 + d2*d2 + d3*d3;
                atomicMax(&dmax[c],     encf(fmaxf(rec00, rec10)));
                atomicMax(&dmax[c + 1], encf(fmaxf(rec01, rec11)));
            }
#pragma unroll
            for (int o = 16; o > 0; o >>= 1)
                lossloc += __shfl_xor_sync(0xffffffffu, lossloc, o);
            if (lane == 0) wsum[wid] = lossloc;
        }
        __syncthreads();
        if (tid < FDC) atomicMax(&g_skl[b*FDC + tid], dmax[tid]);
        if (tid == 0) {
            float s = 0.f;
            for (int w = 0; w < 8; w++) s += wsum[w];
            g_lossPartial[blockIdx.x] = s;
        }
    }
}

// =====================================================================
// Kernel C: 4 blocks; parallelized matvecs (4 thr/out for w1, 2 for w2)
// =====================================================================
__global__ __launch_bounds__(256) void kC(const float* __restrict__ ln_g,
        const float* __restrict__ ln_b, const float* __restrict__ w1,
        const float* __restrict__ b1,   const float* __restrict__ w2,
        const float* __restrict__ b2,   float* __restrict__ out)
{
    __shared__ float red[128];
    __shared__ float hbuf[128];
    __shared__ float h2[64];
    __shared__ float wsum2[8];
    const int tid = threadIdx.x;
    const int b   = blockIdx.x;

    if (b == 0) {
        float s = 0.f;
        for (int i = tid; i < NBLK_B; i += 256) s += g_lossPartial[i];
#pragma unroll
        for (int o = 16; o > 0; o >>= 1) s += __shfl_xor_sync(0xffffffffu, s, o);
        if ((tid & 31) == 0) wsum2[tid >> 5] = s;
        __syncthreads();
        if (tid == 0) {
            float tt = 0.f;
            for (int w = 0; w < 8; w++) tt += wsum2[w];
            out[LOSS_OFF] = tt / ((float)TOK * (float)FDC);
        }
    }

    float x = 0.f;
    if (tid < FDC) { x = decf(g_skl[b*FDC + tid]); red[tid] = x; }
    __syncthreads();
    for (int o = 64; o > 0; o >>= 1) {
        if (tid < o) red[tid] += red[tid + o];
        __syncthreads();
    }
    const float mu = red[0] * (1.f/FDC);
    __syncthreads();
    const float dfx = x - mu;
    if (tid < FDC) red[tid] = dfx*dfx;
    __syncthreads();
    for (int o = 64; o > 0; o >>= 1) {
        if (tid < o) red[tid] += red[tid + o];
        __syncthreads();
    }
    const float var = red[0] * (1.f/FDC);
    __syncthreads();
    if (tid < FDC)
        hbuf[tid] = dfx * rsqrtf(var + 1e-5f) * ln_g[tid] + ln_b[tid];
    __syncthreads();
    {
        const int o = tid >> 2, part = tid & 3;
        float a = 0.f;
        const float* wr = w1 + o*FDC + part*32;
        const float* hb = hbuf + part*32;
#pragma unroll 8
        for (int d = 0; d < 32; ++d) a = fmaf(hb[d], wr[d], a);
        a += __shfl_xor_sync(0xffffffffu, a, 1);
        a += __shfl_xor_sync(0xffffffffu, a, 2);
        if (part == 0) {
            a += b1[o];
            h2[o] = 0.5f * a * (1.f + erff(a * 0.70710678118654752f));
        }
    }
    __syncthreads();
    {
        const int o = tid >> 1, part = tid & 1;
        float a = 0.f;
        if (o < OUTC) {
            const float* wr = w2 + o*(FDC/2) + part*32;
#pragma unroll 8
            for (int e = 0; e < 32; ++e) a = fmaf(h2[part*32 + e], wr[e], a);
        }
        a += __shfl_xor_sync(0xffffffffu, a, 1);
        if (o < OUTC && part == 0) out[b*OUTC + o] = a + b2[o];
    }
}

extern "C" void kernel_launch(void* const* d_in, const int* in_sizes, int n_in,
                              void* d_out, int out_size)
{
    const float* feat  = (const float*)d_in[0];
    const float* seg_w = (const float*)d_in[1];
    const float* seg_b = (const float*)d_in[2];
    const float* pc_w  = (const float*)d_in[3];
    const float* pc_b  = (const float*)d_in[4];
    const float* memw  = (const float*)d_in[5];
    const float* ln_g  = (const float*)d_in[6];
    const float* ln_b  = (const float*)d_in[7];
    const float* w1    = (const float*)d_in[8];
    const float* b1    = (const float*)d_in[9];
    const float* w2    = (const float*)d_in[10];
    const float* b2    = (const float*)d_in[11];
    float* out = (float*)d_out;

    cudaFuncSetAttribute(kAB, cudaFuncAttributeMaxDynamicSharedMemorySize, SMEM_AB);

    kPrep<<<(FDC*JJ*MMS + 255)/256, 256>>>(memw, seg_w, pc_w);
    kAB<<<NBLK_B, 512, SMEM_AB>>>(feat, seg_b, pc_b, out);
    kC<<<4, 256>>>(ln_g, ln_b, w1, b1, w2, b2, out);
}

// round 17
// speedup vs baseline: 1.3166x; 1.3166x over previous
#include <cuda_runtime.h>
#include <cuda_bf16.h>
#include <math.h>
#include <cstdint>

// ---- problem dims ----
#define BB   4
#define LL   24
#define NNP  512
#define DIMC 1024
#define JJ   24
#define MMS  64
#define FDC  128
#define OUTC 72
#define NT   (LL*NNP)
#define TOK  (BB*NT)

#define SEG_OFF  (BB*OUTC)
#define SEG_SIZE (BB*LL*JJ*NNP)
#define LOSS_OFF (SEG_OFF + SEG_SIZE)

#define TBB 128
#define NBLK_B (BB*(NT/TBB))           // 384

// ---- device scratch ----
__device__ __nv_bfloat16 g_mem_hi[FDC*JJ*MMS];    // [d][slot]
__device__ __nv_bfloat16 g_mem_lo[FDC*JJ*MMS];
__device__ __nv_bfloat16 g_w_hi[16*160*64];       // [ktile64][row][k-in-tile]
__device__ __nv_bfloat16 g_w_lo[16*160*64];
__device__ float    g_lossPartial[NBLK_B];
__device__ unsigned g_skl[BB*FDC];

__device__ __forceinline__ unsigned encf(float f) {
    unsigned u = __float_as_uint(f);
    return (u & 0x80000000u) ? ~u : (u | 0x80000000u);
}
__device__ __forceinline__ float decf(unsigned u) {
    return (u & 0x80000000u) ? __uint_as_float(u & 0x7FFFFFFFu)
                             : __uint_as_float(~u);
}

__device__ __forceinline__ uint32_t smem_u32(const void* p) {
    uint32_t a;
    asm("{ .reg .u64 t; cvta.to.shared.u64 t, %1; cvt.u32.u64 %0, t; }" : "=r"(a) : "l"(p));
    return a;
}

// ---- mma (non-volatile: deps carried by "+f" accumulator constraints) ----
__device__ __forceinline__ void mma16816(float* d, const uint32_t* a,
                                         uint32_t b0, uint32_t b1) {
    asm("mma.sync.aligned.m16n8k16.row.col.f32.bf16.bf16.f32 "
        "{%0,%1,%2,%3}, {%4,%5,%6,%7}, {%8,%9}, {%0,%1,%2,%3};"
        : "+f"(d[0]), "+f"(d[1]), "+f"(d[2]), "+f"(d[3])
        : "r"(a[0]), "r"(a[1]), "r"(a[2]), "r"(a[3]), "r"(b0), "r"(b1));
}
#define LDSM_X4(r, a) asm volatile("ldmatrix.sync.aligned.m8n8.x4.shared.b16 {%0,%1,%2,%3}, [%4];" \
    : "=r"((r)[0]),"=r"((r)[1]),"=r"((r)[2]),"=r"((r)[3]) : "r"(a))
#define LDSM_X4T(r, a) asm volatile("ldmatrix.sync.aligned.m8n8.x4.trans.shared.b16 {%0,%1,%2,%3}, [%4];" \
    : "=r"((r)[0]),"=r"((r)[1]),"=r"((r)[2]),"=r"((r)[3]) : "r"(a))
#define CP_ASYNC16(dst, src) asm volatile("cp.async.cg.shared.global [%0], [%1], 16;" :: "r"(dst), "l"(src))
#define CP_COMMIT() asm volatile("cp.async.commit_group;" ::: "memory")
#define CP_WAIT1() asm volatile("cp.async.wait_group 1;" ::: "memory")
#define CP_WAIT0() asm volatile("cp.async.wait_group 0;" ::: "memory")

__device__ __forceinline__ uint32_t pack2(__nv_bfloat16 x, __nv_bfloat16 y) {
    __nv_bfloat162 v; v.x = x; v.y = y;
    return *(uint32_t*)&v;
}
__device__ __forceinline__ void hilo(float v, __nv_bfloat16& h, __nv_bfloat16& l) {
    h = __float2bfloat16(v);
    l = __float2bfloat16(v - __bfloat162float(h));
}

// fused prep: mem -> bf16 hi/lo, W (seg_w|pc_w) -> bf16 hi/lo ktile64-major, g_skl init
__global__ void kPrep(const float* __restrict__ memw,
                      const float* __restrict__ seg_w, const float* __restrict__ pc_w) {
    int i = blockIdx.x*blockDim.x + threadIdx.x;
    if (i < BB*FDC) g_skl[i] = 0u;
    if (i < 16*160*64) {
        const int kk = i & 63, row = (i >> 6) % 160, kt = i / (160*64);
        float v = 0.f;
        if (row < JJ)            v = seg_w[row*DIMC + kt*64 + kk];
        else if (row < JJ + FDC) v = pc_w[(row - JJ)*DIMC + kt*64 + kk];
        __nv_bfloat16 h, l; hilo(v, h, l);
        g_w_hi[i] = h;  g_w_lo[i] = l;
    }
    if (i < FDC*JJ*MMS) {
        float v = memw[i];
        __nv_bfloat16 h, l; hilo(v, h, l);
        g_mem_hi[i] = h;  g_mem_lo[i] = l;
    }
}

// ---- fused kernel smem layout ----
// phase A (proj): 2 buffers of 82944 -> [0, 165888)
#define KA_AH 0
#define KA_AL 18432
#define KA_WH 36864
#define KA_WL 59904
#define KA_BUF 82944
// phase B (forward_mem): A1 tiles overlay kA buf0; B2 bufs overlay the rest
#define OFF_A1H  0          // 128 x 136 bf16 = 34816
#define OFF_A1L  34816
#define OFF_B2H0 69632      // 3 bufs x 18432 -> 124928
#define OFF_B2L0 124928     // 3 bufs x 18432 -> 180224
#define OFF_SEG  180224     // 128*25 floats
#define OFF_PSUM 193024
#define OFF_DMAX 193536
#define OFF_WSUM 194048
#define SMEM_AB  194112

__global__ __launch_bounds__(512, 1) void kAB(const float* __restrict__ feat,
        const float* __restrict__ seg_b, const float* __restrict__ pc_b,
        float* __restrict__ out)
{
    extern __shared__ char sm[];
    const uint32_t smb = smem_u32(sm);
    const int tid  = threadIdx.x;
    const int lane = tid & 31;
    const int wid  = tid >> 5;
    const int t0   = blockIdx.x * 128;
    const int b    = blockIdx.x / (NT/TBB);
    const int n0   = (blockIdx.x % (NT/TBB)) * TBB;

    __nv_bfloat16* A1H = (__nv_bfloat16*)(sm + OFF_A1H);
    __nv_bfloat16* A1L = (__nv_bfloat16*)(sm + OFF_A1L);
    float*    segS  = (float*)(sm + OFF_SEG);
    float*    psumP = (float*)(sm + OFF_PSUM);
    unsigned* dmax  = (unsigned*)(sm + OFF_DMAX);
    float*    wsum  = (float*)(sm + OFF_WSUM);

    auto prefetch = [&](int chn, int bufn) {
        const int k0 = chn*MMS;
        const uint32_t dH = smb + OFF_B2H0 + bufn*18432;
        const uint32_t dL = smb + OFF_B2L0 + bufn*18432;
#pragma unroll
        for (int it = 0; it < 2; it++) {
            const int p = tid + it*512, d = p >> 3, j = p & 7;
            CP_ASYNC16(dH + d*144 + j*16, (const char*)g_mem_hi + ((size_t)d*(JJ*MMS) + k0)*2 + j*16);
            CP_ASYNC16(dL + d*144 + j*16, (const char*)g_mem_lo + ((size_t)d*(JJ*MMS) + k0)*2 + j*16);
        }
    };

    // ================= phase A: seg+pc projection =================
    {
        const int wm   = wid >> 1, wn = wid & 1;
        const int row0 = wm*16, col0 = wn*80;

        const uint32_t offA_lm = (uint32_t)(((lane & 7) + ((lane >> 3) & 1)*8)*144 + (lane >> 4)*16);
        const uint32_t offB_lm = (uint32_t)(((lane & 7) + ((lane >> 4) & 1)*8)*144 + ((lane >> 3) & 1)*16);

        float acc[10][4];
#pragma unroll
        for (int nt = 0; nt < 10; nt++)
#pragma unroll
            for (int r = 0; r < 4; r++) acc[nt][r] = 0.f;

        float4 fA[4];

        auto ldg_tile = [&](int k0) {
#pragma unroll
            for (int it = 0; it < 4; it++) {
                const int p = tid + it*512, r = p >> 4, c4 = (p & 15)*4;
                fA[it] = *(const float4*)&feat[(size_t)(t0 + r)*DIMC + k0 + c4];
            }
        };
        auto sts_tile = [&](int buf) {
            const uint32_t aH = buf*KA_BUF + KA_AH, aL = buf*KA_BUF + KA_AL;
#pragma unroll
            for (int it = 0; it < 4; it++) {
                const int p = tid + it*512, r = p >> 4, c4 = (p & 15)*4;
                const float4 v = fA[it];
                __nv_bfloat16 h0,l0,h1,l1,h2,l2,h3,l3;
                hilo(v.x,h0,l0); hilo(v.y,h1,l1); hilo(v.z,h2,l2); hilo(v.w,h3,l3);
                *(uint2*)(sm + aH + r*144 + c4*2) = uint2{pack2(h0,h1), pack2(h2,h3)};
                *(uint2*)(sm + aL + r*144 + c4*2) = uint2{pack2(l0,l1), pack2(l2,l3)};
            }
        };
        auto cpW = [&](int kt, int buf) {
            const uint32_t wH = smb + buf*KA_BUF + KA_WH;
            const uint32_t wL = smb + buf*KA_BUF + KA_WL;
#pragma unroll
            for (int it2 = 0; it2 < 5; it2++) {
                const int q = tid + it2*512;
                const int qq = q - (q >= 1280 ? 1280 : 0);
                const int r = qq >> 3, j = qq & 7;
                const uint32_t dst = (q >= 1280 ? wL : wH) + r*144 + j*16;
                const char* src = (const char*)(q >= 1280 ? g_w_lo : g_w_hi)
                                + ((size_t)(kt*160 + r)*64 + j*8)*2;
                CP_ASYNC16(dst, src);
            }
        };

        cpW(0, 0); CP_COMMIT();
        ldg_tile(0);
        sts_tile(0);
        CP_WAIT0();
        __syncthreads();

        for (int it = 0; it < 16; it++) {
            const int buf = it & 1;
            if (it < 15) { ldg_tile((it + 1)*64); cpW(it + 1, buf ^ 1); CP_COMMIT(); }

            const uint32_t aH = smb + buf*KA_BUF + KA_AH, aL = smb + buf*KA_BUF + KA_AL;
            const uint32_t wH = smb + buf*KA_BUF + KA_WH, wL = smb + buf*KA_BUF + KA_WL;
#pragma unroll
            for (int ks = 0; ks < 4; ks++) {
                const uint32_t kkB = ks*32;
                uint32_t ah[4], al[4];
                LDSM_X4(ah, aH + offA_lm + row0*144 + kkB);
                LDSM_X4(al, aL + offA_lm + row0*144 + kkB);
#pragma unroll
                for (int ntp = 0; ntp < 5; ntp++) {
                    const uint32_t nOff = (col0 + ntp*16)*144;
                    uint32_t bh[4], bl[4];
                    LDSM_X4(bh, wH + offB_lm + nOff + kkB);
                    LDSM_X4(bl, wL + offB_lm + nOff + kkB);
                    mma16816(acc[2*ntp],   ah, bh[0], bh[1]);
                    mma16816(acc[2*ntp+1], ah, bh[2], bh[3]);
                    mma16816(acc[2*ntp],   ah, bl[0], bl[1]);
                    mma16816(acc[2*ntp+1], ah, bl[2], bl[3]);
                    mma16816(acc[2*ntp],   al, bh[0], bh[1]);
                    mma16816(acc[2*ntp+1], al, bh[2], bh[3]);
                }
            }
            if (it < 15) sts_tile(buf ^ 1);
            CP_WAIT0();
            __syncthreads();
        }

        // kA smem fully dead -> start phase-B mem prefetch (overlaps epilogue)
        prefetch(0, 0); CP_COMMIT();
        prefetch(1, 1); CP_COMMIT();
        if (tid < FDC) dmax[tid] = 0u;

        const int lq = lane >> 2, lr = lane & 3;
        // ---- pc epilogue: cols 24..151 -> A1 smem (hi/lo), no global trip ----
#pragma unroll
        for (int nt = 0; nt < 10; nt++) {
            const int c0 = col0 + nt*8 + lr*2;
            if (c0 < 24 || c0 >= 152) continue;
            const int d = c0 - 24;
#pragma unroll
            for (int half = 0; half < 2; half++) {
                const int row = row0 + lq + half*8;     // local token 0..127
                const float v0 = acc[nt][half*2 + 0] + pc_b[d];
                const float v1 = acc[nt][half*2 + 1] + pc_b[d + 1];
                __nv_bfloat16 h0,l0,h1,l1;
                hilo(v0,h0,l0); hilo(v1,h1,l1);
                *(__nv_bfloat162*)&A1H[row*136 + d] = __nv_bfloat162{h0,h1};
                *(__nv_bfloat162*)&A1L[row*136 + d] = __nv_bfloat162{l0,l1};
            }
        }
        // ---- seg epilogue: softmax -> out (global) + segS (smem) ----
        if (wn == 0) {
#pragma unroll
            for (int half = 0; half < 2; half++) {
                const int row = row0 + lq + half*8;
                float v[6];
#pragma unroll
                for (int nt = 0; nt < 3; nt++)
#pragma unroll
                    for (int q = 0; q < 2; q++)
                        v[nt*2 + q] = acc[nt][half*2 + q] + seg_b[nt*8 + lr*2 + q];
                float mx = v[0];
#pragma unroll
                for (int q = 1; q < 6; q++) mx = fmaxf(mx, v[q]);
                mx = fmaxf(mx, __shfl_xor_sync(0xffffffffu, mx, 1));
                mx = fmaxf(mx, __shfl_xor_sync(0xffffffffu, mx, 2));
                float s = 0.f;
#pragma unroll
                for (int q = 0; q < 6; q++) { v[q] = expf(v[q] - mx); s += v[q]; }
                s += __shfl_xor_sync(0xffffffffu, s, 1);
                s += __shfl_xor_sync(0xffffffffu, s, 2);
                const float inv = 1.f / s;
                const int t = t0 + row;
                const int bb = t / NT; const int rr = t % NT;
                const int l = rr / NNP; const int nn = rr % NNP;
                float* segout = out + SEG_OFF + ((size_t)(bb*LL + l)*JJ)*NNP + nn;
#pragma unroll
                for (int nt = 0; nt < 3; nt++)
#pragma unroll
                    for (int q = 0; q < 2; q++) {
                        const int j = nt*8 + lr*2 + q;
                        const float sv = v[nt*2 + q]*inv;
                        segout[(size_t)j*NNP] = sv;
                        segS[row*25 + j] = sv;
                    }
            }
        }
    }
    __syncthreads();   // A1 + segS visible to all

    // ================= phase B: forward_mem =================
    {
        const int wm   = wid & 7;
        const int h    = wid >> 3;
        const int row0 = wm*16;
        const int g    = lane >> 2, t = lane & 3;

        const uint32_t offA1_lm = (uint32_t)((row0 + (lane & 7) + ((lane >> 3) & 1)*8)*272 + (lane >> 4)*16);
        const uint32_t offB1t4 = (uint32_t)(((lane & 7) + ((lane >> 3) & 1)*8)*144 + (lane >> 4)*16);
        const uint32_t offB2n4 = (uint32_t)((lane & 7)*144 + ((lane >> 3) & 1)*16 + (lane >> 4)*1152);

        float racc[16][4];
#pragma unroll
        for (int nt = 0; nt < 16; nt++)
#pragma unroll
            for (int r = 0; r < 4; r++) racc[nt][r] = 0.f;
        float psum0 = 0.f, psum1 = 0.f;
        const float invs = 0.088388347648318447f;

        for (int ch = 0; ch < JJ; ++ch) {
            if (ch == JJ - 1) CP_WAIT0(); else CP_WAIT1();
            __syncthreads();
            if (ch < JJ - 2) { prefetch(ch + 2, (ch + 2) % 3); CP_COMMIT(); }

            const int buf = ch % 3;
            const uint32_t b2h = smb + OFF_B2H0 + buf*18432;
            const uint32_t b2l = smb + OFF_B2L0 + buf*18432;

            // ---- MMA1: logits[16 tok x 32 slots (this half)], K=128 ----
            float lacc[4][4];
#pragma unroll
            for (int nt = 0; nt < 4; nt++)
#pragma unroll
                for (int r = 0; r < 4; r++) lacc[nt][r] = 0.f;
#pragma unroll
            for (int ks = 0; ks < 8; ks++) {
                uint32_t ah[4], al[4];
                LDSM_X4(ah, smb + OFF_A1H + offA1_lm + ks*32);
                LDSM_X4(al, smb + OFF_A1L + offA1_lm + ks*32);
                uint32_t bh0[4], bl0[4], bh1[4], bl1[4];
                LDSM_X4T(bh0, b2h + offB1t4 + ks*2304 + (h*2 + 0)*32);
                LDSM_X4T(bl0, b2l + offB1t4 + ks*2304 + (h*2 + 0)*32);
                LDSM_X4T(bh1, b2h + offB1t4 + ks*2304 + (h*2 + 1)*32);
                LDSM_X4T(bl1, b2l + offB1t4 + ks*2304 + (h*2 + 1)*32);
                mma16816(lacc[0], ah, bh0[0], bh0[1]);
                mma16816(lacc[1], ah, bh0[2], bh0[3]);
                mma16816(lacc[2], ah, bh1[0], bh1[1]);
                mma16816(lacc[3], ah, bh1[2], bh1[3]);
                mma16816(lacc[0], ah, bl0[0], bl0[1]);
                mma16816(lacc[1], ah, bl0[2], bl0[3]);
                mma16816(lacc[2], ah, bl1[0], bl1[1]);
                mma16816(lacc[3], ah, bl1[2], bl1[3]);
                mma16816(lacc[0], al, bh0[0], bh0[1]);
                mma16816(lacc[1], al, bh0[2], bh0[3]);
                mma16816(lacc[2], al, bh1[0], bh1[1]);
                mma16816(lacc[3], al, bh1[2], bh1[3]);
            }

            // ---- exp + pack attn A-fragments ----
            const float sv0 = segS[(row0 + g)*25 + ch] * invs;
            const float sv1 = segS[(row0 + g + 8)*25 + ch] * invs;
            uint32_t aHf[2][4], aLf[2][4];
#pragma unroll
            for (int nt = 0; nt < 4; nt++) {
                const float p0 = __expf(lacc[nt][0]*sv0);
                const float p1 = __expf(lacc[nt][1]*sv0);
                const float p2 = __expf(lacc[nt][2]*sv1);
                const float p3 = __expf(lacc[nt][3]*sv1);
                psum0 += p0 + p1;  psum1 += p2 + p3;
                __nv_bfloat16 h0,l0,h1,l1,h2,l2,h3,l3;
                hilo(p0,h0,l0); hilo(p1,h1,l1); hilo(p2,h2,l2); hilo(p3,h3,l3);
                const int ks2 = nt >> 1, hf = nt & 1;
                aHf[ks2][hf*2 + 0] = pack2(h0, h1);
                aHf[ks2][hf*2 + 1] = pack2(h2, h3);
                aLf[ks2][hf*2 + 0] = pack2(l0, l1);
                aLf[ks2][hf*2 + 1] = pack2(l2, l3);
            }

            // ---- MMA2: rec += attn @ mem, K = this half's 32 slots ----
#pragma unroll
            for (int ks2 = 0; ks2 < 2; ks2++) {
                const uint32_t kbyte = h*64 + ks2*32;
#pragma unroll
                for (int qp = 0; qp < 4; qp++) {
                    const int q0 = qp*2, q1 = qp*2 + 1;
                    uint32_t bh0[4], bl0[4], bh1[4], bl1[4];
                    LDSM_X4(bh0, b2h + offB2n4 + q0*2304 + kbyte);
                    LDSM_X4(bl0, b2l + offB2n4 + q0*2304 + kbyte);
                    LDSM_X4(bh1, b2h + offB2n4 + q1*2304 + kbyte);
                    LDSM_X4(bl1, b2l + offB2n4 + q1*2304 + kbyte);
                    mma16816(racc[2*q0],   aHf[ks2], bh0[0], bh0[1]);
                    mma16816(racc[2*q0+1], aHf[ks2], bh0[2], bh0[3]);
                    mma16816(racc[2*q1],   aHf[ks2], bh1[0], bh1[1]);
                    mma16816(racc[2*q1+1], aHf[ks2], bh1[2], bh1[3]);
                    mma16816(racc[2*q0],   aHf[ks2], bl0[0], bl0[1]);
                    mma16816(racc[2*q0+1], aHf[ks2], bl0[2], bl0[3]);
                    mma16816(racc[2*q1],   aHf[ks2], bl1[0], bl1[1]);
                    mma16816(racc[2*q1+1], aHf[ks2], bl1[2], bl1[3]);
                    mma16816(racc[2*q0],   aLf[ks2], bh0[0], bh0[1]);
                    mma16816(racc[2*q0+1], aLf[ks2], bh0[2], bh0[3]);
                    mma16816(racc[2*q1],   aLf[ks2], bh1[0], bh1[1]);
                    mma16816(racc[2*q1+1], aLf[ks2], bh1[2], bh1[3]);
                }
            }
        }

        psum0 += __shfl_xor_sync(0xffffffffu, psum0, 1);
        psum0 += __shfl_xor_sync(0xffffffffu, psum0, 2);
        psum1 += __shfl_xor_sync(0xffffffffu, psum1, 1);
        psum1 += __shfl_xor_sync(0xffffffffu, psum1, 2);

        __syncthreads();
        float* rs = (float*)(sm + OFF_B2H0);   // [128 tok][130] floats
        if (h == 1) {
            if (t == 0) { psumP[row0 + g] = psum0; psumP[row0 + g + 8] = psum1; }
#pragma unroll
            for (int nt = 0; nt < 16; nt++) {
                const int c = nt*8 + t*2;
                *(float2*)&rs[(row0 + g)*130 + c]     = float2{racc[nt][0], racc[nt][1]};
                *(float2*)&rs[(row0 + g + 8)*130 + c] = float2{racc[nt][2], racc[nt][3]};
            }
        }
        __syncthreads();

        if (h == 0) {
            const float inv0 = 1.f / (psum0 + psumP[row0 + g]);
            const float inv1 = 1.f / (psum1 + psumP[row0 + g + 8]);
            float lossloc = 0.f;
            const int r0g = row0 + g, r1g = row0 + g + 8;
#pragma unroll
            for (int nt = 0; nt < 16; nt++) {
                const int c = nt*8 + t*2;
                const float2 o0 = *(const float2*)&rs[r0g*130 + c];
                const float2 o1 = *(const float2*)&rs[r1g*130 + c];
                const float rec00 = (racc[nt][0] + o0.x)*inv0, rec01 = (racc[nt][1] + o0.y)*inv0;
                const float rec10 = (racc[nt][2] + o1.x)*inv1, rec11 = (racc[nt][3] + o1.y)*inv1;
                const __nv_bfloat162 ph0 = *(const __nv_bfloat162*)&A1H[r0g*136 + c];
                const __nv_bfloat162 pl0 = *(const __nv_bfloat162*)&A1L[r0g*136 + c];
                const __nv_bfloat162 ph1 = *(const __nv_bfloat162*)&A1H[r1g*136 + c];
                const __nv_bfloat162 pl1 = *(const __nv_bfloat162*)&A1L[r1g*136 + c];
                const float d0 = rec00 - (__bfloat162float(ph0.x) + __bfloat162float(pl0.x));
                const float d1 = rec01 - (__bfloat162float(ph0.y) + __bfloat162float(pl0.y));
                const float d2 = rec10 - (__bfloat162float(ph1.x) + __bfloat162float(pl1.x));
                const float d3 = rec11 - (__bfloat162float(ph1.y) + __bfloat162float(pl1.y));
                lossloc += d0*d0 + d1*d1 + d2*d2 + d3*d3;
                atomicMax(&dmax[c],     encf(fmaxf(rec00, rec10)));
                atomicMax(&dmax[c + 1], encf(fmaxf(rec01, rec11)));
            }
#pragma unroll
            for (int o = 16; o > 0; o >>= 1)
                lossloc += __shfl_xor_sync(0xffffffffu, lossloc, o);
            if (lane == 0) wsum[wid] = lossloc;
        }
        __syncthreads();
        if (tid < FDC) atomicMax(&g_skl[b*FDC + tid], dmax[tid]);
        if (tid == 0) {
            float s = 0.f;
            for (int w = 0; w < 8; w++) s += wsum[w];
            g_lossPartial[blockIdx.x] = s;
        }
    }
}

// =====================================================================
// Kernel C: 4 blocks; parallelized matvecs (4 thr/out for w1, 2 for w2)
// =====================================================================
__global__ __launch_bounds__(256) void kC(const float* __restrict__ ln_g,
        const float* __restrict__ ln_b, const float* __restrict__ w1,
        const float* __restrict__ b1,   const float* __restrict__ w2,
        const float* __restrict__ b2,   float* __restrict__ out)
{
    __shared__ float red[128];
    __shared__ float hbuf[128];
    __shared__ float h2[64];
    __shared__ float wsum2[8];
    const int tid = threadIdx.x;
    const int b   = blockIdx.x;

    if (b == 0) {
        float s = 0.f;
        for (int i = tid; i < NBLK_B; i += 256) s += g_lossPartial[i];
#pragma unroll
        for (int o = 16; o > 0; o >>= 1) s += __shfl_xor_sync(0xffffffffu, s, o);
        if ((tid & 31) == 0) wsum2[tid >> 5] = s;
        __syncthreads();
        if (tid == 0) {
            float tt = 0.f;
            for (int w = 0; w < 8; w++) tt += wsum2[w];
            out[LOSS_OFF] = tt / ((float)TOK * (float)FDC);
        }
    }

    float x = 0.f;
    if (tid < FDC) { x = decf(g_skl[b*FDC + tid]); red[tid] = x; }
    __syncthreads();
    for (int o = 64; o > 0; o >>= 1) {
        if (tid < o) red[tid] += red[tid + o];
        __syncthreads();
    }
    const float mu = red[0] * (1.f/FDC);
    __syncthreads();
    const float dfx = x - mu;
    if (tid < FDC) red[tid] = dfx*dfx;
    __syncthreads();
    for (int o = 64; o > 0; o >>= 1) {
        if (tid < o) red[tid] += red[tid + o];
        __syncthreads();
    }
    const float var = red[0] * (1.f/FDC);
    __syncthreads();
    if (tid < FDC)
        hbuf[tid] = dfx * rsqrtf(var + 1e-5f) * ln_g[tid] + ln_b[tid];
    __syncthreads();
    // ---- w1: 256 threads, 4 per output (quad shuffle reduce) ----
    {
        const int o = tid >> 2, part = tid & 3;
        float a = 0.f;
        const float* wr = w1 + o*FDC + part*32;
        const float* hb = hbuf + part*32;
#pragma unroll 8
        for (int d = 0; d < 32; ++d) a = fmaf(hb[d], wr[d], a);
        a += __shfl_xor_sync(0xffffffffu, a, 1);
        a += __shfl_xor_sync(0xffffffffu, a, 2);
        if (part == 0) {
            a += b1[o];
            h2[o] = 0.5f * a * (1.f + erff(a * 0.70710678118654752f));
        }
    }
    __syncthreads();
    // ---- w2: 144 active threads, 2 per output (pair shuffle reduce) ----
    {
        const int o = tid >> 1, part = tid & 1;
        float a = 0.f;
        if (o < OUTC) {
            const float* wr = w2 + o*(FDC/2) + part*32;
#pragma unroll 8
            for (int e = 0; e < 32; ++e) a = fmaf(h2[part*32 + e], wr[e], a);
        }
        a += __shfl_xor_sync(0xffffffffu, a, 1);
        if (o < OUTC && part == 0) out[b*OUTC + o] = a + b2[o];
    }
}

extern "C" void kernel_launch(void* const* d_in, const int* in_sizes, int n_in,
                              void* d_out, int out_size)
{
    const float* feat  = (const float*)d_in[0];
    const float* seg_w = (const float*)d_in[1];
    const float* seg_b = (const float*)d_in[2];
    const float* pc_w  = (const float*)d_in[3];
    const float* pc_b  = (const float*)d_in[4];
    const float* memw  = (const float*)d_in[5];
    const float* ln_g  = (const float*)d_in[6];
    const float* ln_b  = (const float*)d_in[7];
    const float* w1    = (const float*)d_in[8];
    const float* b1    = (const float*)d_in[9];
    const float* w2    = (const float*)d_in[10];
    const float* b2    = (const float*)d_in[11];
    float* out = (float*)d_out;

    cudaFuncSetAttribute(kAB, cudaFuncAttributeMaxDynamicSharedMemorySize, SMEM_AB);

    kPrep<<<(FDC*JJ*MMS + 255)/256, 256>>>(memw, seg_w, pc_w);
    kAB<<<NBLK_B, 512, SMEM_AB>>>(feat, seg_b, pc_b, out);
    kC<<<4, 256>>>(ln_g, ln_b, w1, b1, w2, b2, out);
}